// round 3
// baseline (speedup 1.0000x reference)
#include <cuda_runtime.h>
#include <math.h>

#define NSLOPE 0.2f
#define NN 1024
#define F 128

__device__ float g_X[NN * F];
__device__ float g_Y[NN * F];
__device__ float g_H[NN * F];
__device__ float g_asf[NN];
__device__ float g_adf[NN];

__device__ __forceinline__ float lrelu(float x) { return x > 0.f ? x : NSLOPE * x; }

// ---------------------------------------------------------------------------
// GEMM: H = X @ W.  grid 128: (row-block 0..63) x (col-half 0..1).
// block 128 threads = 64 cols x 2 row-halves; 16 rows/block, 8 rows/thread.
// W slice transposed into smem (stride 129 -> conflict-free LDS); x rows
// broadcast via LDS.128. Inner loop is FMA-rt bound (pipe saturated at 4 warps).
template <bool CONCAT>
__global__ void gemmT(const float* __restrict__ X, const float* __restrict__ d1,
                      const float* __restrict__ d2, const float* __restrict__ W,
                      float* __restrict__ H) {
    __shared__ float Wt[64 * 129];
    __shared__ __align__(16) float xs[16][128];
    int tid = threadIdx.x;
    int bx = blockIdx.x;
    int cs = (bx & 1) * 64;
    int n0 = (bx >> 1) * 16;
    int c = tid & 63;
    int rh = tid >> 6;

    // load W[k][cs..cs+63], k=0..127, transposed into Wt[c][k]
#pragma unroll
    for (int i = 0; i < 16; i++) {
        int f = tid + i * 128;
        int k = f >> 4, cq = f & 15;
        float4 w4 = *reinterpret_cast<const float4*>(W + k * F + cs + cq * 4);
        Wt[(cq * 4 + 0) * 129 + k] = w4.x;
        Wt[(cq * 4 + 1) * 129 + k] = w4.y;
        Wt[(cq * 4 + 2) * 129 + k] = w4.z;
        Wt[(cq * 4 + 3) * 129 + k] = w4.w;
    }
    // load 16 rows of X (or desc1/desc2 when CONCAT)
#pragma unroll
    for (int i = 0; i < 4; i++) {
        int f = tid + i * 128;
        int r = f >> 5, cq = f & 31;
        int n = n0 + r;
        float4 x4;
        if (CONCAT) {
            x4 = (n < 512) ? reinterpret_cast<const float4*>(d1)[n * 32 + cq]
                           : reinterpret_cast<const float4*>(d2)[(n - 512) * 32 + cq];
        } else {
            x4 = reinterpret_cast<const float4*>(X)[n * 32 + cq];
        }
        *reinterpret_cast<float4*>(&xs[r][cq * 4]) = x4;
    }
    __syncthreads();

    float acc[8] = {0, 0, 0, 0, 0, 0, 0, 0};
#pragma unroll 4
    for (int kq = 0; kq < 32; kq++) {
        float w0 = Wt[c * 129 + kq * 4 + 0];
        float w1 = Wt[c * 129 + kq * 4 + 1];
        float w2 = Wt[c * 129 + kq * 4 + 2];
        float w3 = Wt[c * 129 + kq * 4 + 3];
#pragma unroll
        for (int r = 0; r < 8; r++) {
            float4 x = *reinterpret_cast<const float4*>(&xs[rh * 8 + r][kq * 4]);
            acc[r] = fmaf(x.x, w0, fmaf(x.y, w1, fmaf(x.z, w2, fmaf(x.w, w3, acc[r]))));
        }
    }
#pragma unroll
    for (int r = 0; r < 8; r++) H[(n0 + rh * 8 + r) * F + cs + c] = acc[r];
}

// ---------------------------------------------------------------------------
__device__ __forceinline__ float2 warp_incl_scan2(float2 v, int lane) {
#pragma unroll
    for (int d = 1; d < 32; d <<= 1) {
        float x = __shfl_up_sync(0xffffffffu, v.x, d);
        float y = __shfl_up_sync(0xffffffffu, v.y, d);
        if (lane >= d) { v.x += x; v.y += y; }
    }
    return v;
}
__device__ __forceinline__ float2 warp_incl_sufscan2(float2 v, int lane) {
#pragma unroll
    for (int d = 1; d < 32; d <<= 1) {
        float x = __shfl_down_sync(0xffffffffu, v.x, d);
        float y = __shfl_down_sync(0xffffffffu, v.y, d);
        if (lane + d < 32) { v.x += x; v.y += y; }
    }
    return v;
}

__device__ __forceinline__ void ce(float& a, float& va, float& b, float& vb, bool up) {
    if ((a > b) == up) {
        float t = a; a = b; b = t;
        float tv = va; va = vb; vb = tv;
    }
}

// ---------------------------------------------------------------------------
// GAT attention (128 heads, C=1), 4 heads per block (512 threads, 4 lockstep
// groups of 128). Register/shuffle bitonic sort of 512 src scores per head,
// exact suffix sums (positive branch) / exclusive prefix sums (negative
// branch), per-dst 9-step binary search + 2 table lookups. ELU fused.
template <bool CROSS>
__global__ void attn4(const float* __restrict__ H, const float* __restrict__ a_src,
                      const float* __restrict__ a_dst, const float* __restrict__ bias,
                      float* __restrict__ Xout) {
    __shared__ float sA[4][512];
    __shared__ __align__(16) float pool[4 * 513 * 4];  // sStage / sort-payload / sSP / out
    __shared__ float2 wt1[4][4], wt2[4][4];

    int tid = threadIdx.x;
    int hg = tid >> 7;      // head group 0..3
    int t = tid & 127;      // index within group
    int lane = tid & 31;
    int w = t >> 5;
    int h0 = blockIdx.x * 4;
    int h = h0 + hg;
    int dg = blockIdx.y;
    int sg = CROSS ? (1 - dg) : dg;

    float asrc = a_src[h], adst = a_dst[h], bh = bias[h];

    // stage src + dst H columns (float4 per node) into smem, then to registers
    {
        float4 s4 = *reinterpret_cast<const float4*>(H + (sg * 512 + tid) * F + h0);
        float4 d4 = *reinterpret_cast<const float4*>(H + (dg * 512 + tid) * F + h0);
        pool[0 * 512 + tid] = s4.x; pool[1 * 512 + tid] = s4.y;
        pool[2 * 512 + tid] = s4.z; pool[3 * 512 + tid] = s4.w;
        sA[0][tid] = d4.x; sA[1][tid] = d4.y; sA[2][tid] = d4.z; sA[3][tid] = d4.w;
    }
    __syncthreads();

    float k[4], v[4], Hd[4];
    {
        float4 v4 = *reinterpret_cast<const float4*>(&pool[hg * 512 + t * 4]);
        float4 h4 = *reinterpret_cast<const float4*>(&sA[hg][t * 4]);
        v[0] = v4.x; v[1] = v4.y; v[2] = v4.z; v[3] = v4.w;
        Hd[0] = h4.x; Hd[1] = h4.y; Hd[2] = h4.z; Hd[3] = h4.w;
#pragma unroll
        for (int e = 0; e < 4; e++) k[e] = v[e] * asrc;
    }

    // bitonic sort ascending; element i = t*4+e
    for (int K2 = 2; K2 <= 512; K2 <<= 1) {
        for (int J = K2 >> 1; J >= 4; J >>= 1) {
            bool up = (((t * 4) & K2) == 0);
            if (J >= 128) {
                int d = J >> 2;  // thread distance
                bool low = ((t & d) == 0);
                bool want_small = (low == up);
                __syncthreads();
#pragma unroll
                for (int e = 0; e < 4; e++) {
                    sA[hg][t * 4 + e] = k[e];
                    pool[hg * 512 + t * 4 + e] = v[e];
                }
                __syncthreads();
#pragma unroll
                for (int e = 0; e < 4; e++) {
                    int p = (t * 4 + e) ^ J;
                    float ko = sA[hg][p];
                    float vo = pool[hg * 512 + p];
                    bool take = want_small ? (ko < k[e]) : (ko > k[e]);
                    if (take) { k[e] = ko; v[e] = vo; }
                }
            } else {
                int d = J >> 2;  // lane distance 1..16
                bool low = ((t & d) == 0);
                bool want_small = (low == up);
#pragma unroll
                for (int e = 0; e < 4; e++) {
                    float ko = __shfl_xor_sync(0xffffffffu, k[e], d);
                    float vo = __shfl_xor_sync(0xffffffffu, v[e], d);
                    bool take = want_small ? (ko < k[e]) : (ko > k[e]);
                    if (take) { k[e] = ko; v[e] = vo; }
                }
            }
        }
        if (K2 == 2) {
            ce(k[0], v[0], k[1], v[1], true);
            ce(k[2], v[2], k[3], v[3], false);
        } else {
            bool up = (((t * 4) & K2) == 0);
            ce(k[0], v[0], k[2], v[2], up);
            ce(k[1], v[1], k[3], v[3], up);
            ce(k[0], v[0], k[1], v[1], up);
            ce(k[2], v[2], k[3], v[3], up);
        }
    }

    // publish sorted keys for binary search
    __syncthreads();  // protect pool/sA from sort's last cross-stage readers
#pragma unroll
    for (int e = 0; e < 4; e++) sA[hg][t * 4 + e] = k[e];
    __syncthreads();
    float M = sA[hg][511];

    // local scans over thread's 4 sorted elements
    float2 tp1[4], lp2[4], lp1[4];
    float2 c2 = make_float2(0.f, 0.f);
#pragma unroll
    for (int e = 0; e < 4; e++) {
        float q1 = __expf(k[e] - M);
        float q2 = __expf(NSLOPE * (k[e] - M));
        tp1[e] = make_float2(q1, q1 * v[e]);
        c2.x += q2; c2.y += q2 * v[e];
        lp2[e] = c2;
    }
    float2 c1 = make_float2(0.f, 0.f);
#pragma unroll
    for (int e = 3; e >= 0; e--) {
        c1.x += tp1[e].x; c1.y += tp1[e].y;
        lp1[e] = c1;
    }

    float2 tincl = warp_incl_scan2(lp2[3], lane);
    float2 texcl;
    texcl.x = __shfl_up_sync(0xffffffffu, tincl.x, 1);
    texcl.y = __shfl_up_sync(0xffffffffu, tincl.y, 1);
    if (lane == 0) texcl = make_float2(0.f, 0.f);
    if (lane == 31) wt2[hg][w] = tincl;

    float2 sincl = warp_incl_sufscan2(lp1[0], lane);
    float2 sexcl;
    sexcl.x = __shfl_down_sync(0xffffffffu, sincl.x, 1);
    sexcl.y = __shfl_down_sync(0xffffffffu, sincl.y, 1);
    if (lane == 31) sexcl = make_float2(0.f, 0.f);
    if (lane == 0) wt1[hg][w] = sincl;
    __syncthreads();

    float2 base2 = texcl, base1 = sexcl;
#pragma unroll
    for (int ww = 0; ww < 4; ww++) {
        if (ww < w) { base2.x += wt2[hg][ww].x; base2.y += wt2[hg][ww].y; }
        if (ww > w) { base1.x += wt1[hg][ww].x; base1.y += wt1[hg][ww].y; }
    }
    float4* sSP = reinterpret_cast<float4*>(pool);  // [hg][j]: (suf1, suf1v, pre2, pre2v)
#pragma unroll
    for (int e = 0; e < 4; e++) {
        int j = t * 4 + e;
        float2 pre = base2;
        if (e > 0) { pre.x += lp2[e - 1].x; pre.y += lp2[e - 1].y; }
        sSP[hg * 513 + j] =
            make_float4(base1.x + lp1[e].x, base1.y + lp1[e].y, pre.x, pre.y);
    }
    if (t == 127)
        sSP[hg * 513 + 512] =
            make_float4(0.f, 0.f, base2.x + lp2[3].x, base2.y + lp2[3].y);
    __syncthreads();

    // per-dst: binary search rank of threshold -ad, combine branch sums
    float adv[4], th[4];
    int pos[4];
#pragma unroll
    for (int e = 0; e < 4; e++) {
        adv[e] = Hd[e] * adst;
        th[e] = -adv[e];
        pos[e] = 0;
    }
#pragma unroll
    for (int half = 256; half >= 1; half >>= 1) {
#pragma unroll
        for (int e = 0; e < 4; e++)
            if (sA[hg][pos[e] + half - 1] <= th[e]) pos[e] += half;
    }
#pragma unroll
    for (int e = 0; e < 4; e++)
        if (sA[hg][pos[e]] <= th[e]) pos[e]++;

    float oval[4];
#pragma unroll
    for (int e = 0; e < 4; e++) {
        float4 S = sSP[hg * 513 + pos[e]];
        float ad = adv[e];
        float T = M + ad;
        float tmax = T, ts = 0.f;
        if (CROSS) {
            ts = Hd[e] * asrc + ad;
            tmax = fmaxf(tmax, ts);
        }
        float C = lrelu(tmax);
        float f1 = __expf(T - C);
        float f2 = __expf(NSLOPE * T - C);
        float num = f1 * S.y + f2 * S.w;
        float den = f1 * S.x + f2 * S.z;
        if (CROSS) {
            float ws = __expf(lrelu(ts) - C);
            num = fmaf(ws, Hd[e], num);
            den += ws;
        }
        float o = num / (den + 1e-16f) + bh;
        oval[e] = o > 0.f ? o : expm1f(o);  // ELU
    }
    __syncthreads();  // all sSP reads done before overwriting pool with outputs
    *reinterpret_cast<float4*>(&pool[hg * 512 + t * 4]) =
        make_float4(oval[0], oval[1], oval[2], oval[3]);
    __syncthreads();
    {
        int n = tid;  // 512 dst nodes
        float4 q = make_float4(pool[0 * 512 + n], pool[1 * 512 + n],
                               pool[2 * 512 + n], pool[3 * 512 + n]);
        *reinterpret_cast<float4*>(Xout + (dg * 512 + n) * F + h0) = q;
    }
}

// ---------------------------------------------------------------------------
__global__ void dots_kernel(const float* __restrict__ H, const float* __restrict__ a_s,
                            const float* __restrict__ a_d, float* __restrict__ asf,
                            float* __restrict__ adf) {
    int n = blockIdx.x, t = threadIdx.x;
    float h = H[n * F + t];
    float s1 = h * a_s[t];
    float s2 = h * a_d[t];
#pragma unroll
    for (int o = 16; o; o >>= 1) {
        s1 += __shfl_xor_sync(0xffffffffu, s1, o);
        s2 += __shfl_xor_sync(0xffffffffu, s2, o);
    }
    __shared__ float r1[4], r2[4];
    if ((t & 31) == 0) { r1[t >> 5] = s1; r2[t >> 5] = s2; }
    __syncthreads();
    if (t == 0) {
        asf[n] = r1[0] + r1[1] + r1[2] + r1[3];
        adf[n] = r2[0] + r2[1] + r2[2] + r2[3];
    }
}

// final cross-attention: 8 dsts/block, 256 threads (128 cols x 2 s-halves)
__global__ void final_attn(const float* __restrict__ H, const float* __restrict__ asf,
                           const float* __restrict__ adf, const float* __restrict__ bias,
                           float* __restrict__ out) {
    int d0 = blockIdx.x * 8;
    int dg = d0 >> 9;
    int sg = 1 - dg;
    int tid = threadIdx.x;
    int col = tid & 127, sh = tid >> 7;
    int w = tid >> 5, lane = tid & 31;

    __shared__ float sAsf[512];
    __shared__ float4 swq[512][2];
    __shared__ float sAdf[8], sM[8], sSelf[8], sDen[8];
    __shared__ float pr[8][128];
    __shared__ float dred[8][256];
    __shared__ float red[8];

    float mloc = -1e30f;
    for (int s = tid; s < 512; s += 256) {
        float v = asf[sg * 512 + s];
        sAsf[s] = v;
        mloc = fmaxf(mloc, v);
    }
#pragma unroll
    for (int o = 16; o; o >>= 1) mloc = fmaxf(mloc, __shfl_xor_sync(0xffffffffu, mloc, o));
    if (lane == 0) red[w] = mloc;
    __syncthreads();
    float maxasf = red[0];
#pragma unroll
    for (int ww = 1; ww < 8; ww++) maxasf = fmaxf(maxasf, red[ww]);

    if (tid < 8) {
        int dn = d0 + tid;
        float ad = adf[dn];
        float ts = asf[dn] + ad;
        float tmax = fmaxf(maxasf + ad, ts);
        float mm = lrelu(tmax);
        sAdf[tid] = ad;
        sM[tid] = mm;
        sSelf[tid] = __expf(lrelu(ts) - mm);
    }
    __syncthreads();

    float dl[8] = {0, 0, 0, 0, 0, 0, 0, 0};
    for (int s = tid; s < 512; s += 256) {
        float a = sAsf[s];
        float wv[8];
#pragma unroll
        for (int d = 0; d < 8; d++) {
            wv[d] = __expf(lrelu(a + sAdf[d]) - sM[d]);
            dl[d] += wv[d];
        }
        swq[s][0] = make_float4(wv[0], wv[1], wv[2], wv[3]);
        swq[s][1] = make_float4(wv[4], wv[5], wv[6], wv[7]);
    }
#pragma unroll
    for (int d = 0; d < 8; d++) dred[d][tid] = dl[d];
    __syncthreads();
    {
        float x = dred[w][lane] + dred[w][lane + 32] + dred[w][lane + 64] + dred[w][lane + 96] +
                  dred[w][lane + 128] + dred[w][lane + 160] + dred[w][lane + 192] + dred[w][lane + 224];
#pragma unroll
        for (int o = 16; o; o >>= 1) x += __shfl_xor_sync(0xffffffffu, x, o);
        if (lane == 0) sDen[w] = x;
    }
    __syncthreads();

    float acc[8] = {0, 0, 0, 0, 0, 0, 0, 0};
    const float* Hs = H + (sg * 512 + sh * 256) * F + col;
#pragma unroll 2
    for (int s = 0; s < 256; s++) {
        float hv = Hs[s * F];
        int ss = sh * 256 + s;
        float4 w0 = swq[ss][0];
        float4 w1 = swq[ss][1];
        acc[0] = fmaf(w0.x, hv, acc[0]);
        acc[1] = fmaf(w0.y, hv, acc[1]);
        acc[2] = fmaf(w0.z, hv, acc[2]);
        acc[3] = fmaf(w0.w, hv, acc[3]);
        acc[4] = fmaf(w1.x, hv, acc[4]);
        acc[5] = fmaf(w1.y, hv, acc[5]);
        acc[6] = fmaf(w1.z, hv, acc[6]);
        acc[7] = fmaf(w1.w, hv, acc[7]);
    }
    if (sh) {
#pragma unroll
        for (int d = 0; d < 8; d++) pr[d][col] = acc[d];
    }
    __syncthreads();
    if (!sh) {
        float bc = bias[col];
#pragma unroll
        for (int d = 0; d < 8; d++) {
            int dn = d0 + d;
            float Hdv = H[dn * F + col];
            float num = acc[d] + pr[d][col] + sSelf[d] * Hdv;
            out[dn * F + col] = num / (sDen[d] + sSelf[d] + 1e-16f) + bc;
        }
    }
}

// ---------------------------------------------------------------------------
extern "C" void kernel_launch(void* const* d_in, const int* in_sizes, int n_in,
                              void* d_out, int out_size) {
    const float* desc1 = (const float*)d_in[0];
    const float* desc2 = (const float*)d_in[1];
    const float* W1 = (const float*)d_in[2];
    const float* as1 = (const float*)d_in[3];
    const float* ad1 = (const float*)d_in[4];
    const float* b1 = (const float*)d_in[5];
    const float* W2 = (const float*)d_in[6];
    const float* as2 = (const float*)d_in[7];
    const float* ad2 = (const float*)d_in[8];
    const float* b2 = (const float*)d_in[9];
    float* out = (float*)d_out;

    float *X, *Y, *H, *asf, *adf;
    cudaGetSymbolAddress((void**)&X, g_X);
    cudaGetSymbolAddress((void**)&Y, g_Y);
    cudaGetSymbolAddress((void**)&H, g_H);
    cudaGetSymbolAddress((void**)&asf, g_asf);
    cudaGetSymbolAddress((void**)&adf, g_adf);

    dim3 ag(32, 2);
    // conv1: inside (concat fused)
    gemmT<true><<<128, 128>>>(nullptr, desc1, desc2, W1, H);
    attn4<false><<<ag, 512>>>(H, as1, ad1, b1, Y);
    // conv2: cross
    gemmT<false><<<128, 128>>>(Y, nullptr, nullptr, W1, H);
    attn4<true><<<ag, 512>>>(H, as1, ad1, b1, X);
    // conv3: inside
    gemmT<false><<<128, 128>>>(X, nullptr, nullptr, W1, H);
    attn4<false><<<ag, 512>>>(H, as1, ad1, b1, Y);
    // conv4: cross
    gemmT<false><<<128, 128>>>(Y, nullptr, nullptr, W1, H);
    attn4<true><<<ag, 512>>>(H, as1, ad1, b1, X);
    // final conv: cross, heads=1, out_ch=128, no ELU
    gemmT<false><<<128, 128>>>(X, nullptr, nullptr, W2, H);
    dots_kernel<<<1024, 128>>>(H, as2, ad2, asf, adf);
    final_attn<<<128, 256>>>(H, asf, adf, b2, out);
}

// round 5
// speedup vs baseline: 1.0876x; 1.0876x over previous
#include <cuda_runtime.h>
#include <math.h>

#define NSLOPE 0.2f
#define NN 1024
#define F 128

__device__ float g_XT[NN * F];   // feature-major activations [f][n]
__device__ float g_HT[NN * F];   // feature-major conv features [f][n]
__device__ float g_H[NN * F];    // row-major (final conv only)
__device__ float g_asf[NN];
__device__ float g_adf[NN];

__device__ __forceinline__ float lrelu(float x) { return x > 0.f ? x : NSLOPE * x; }

// ---------------------------------------------------------------------------
// GEMM. grid 128: (row-block 0..63) x (col-half 0..1); block 128 threads.
// 16 rows x 64 cols per block, 8 rows/thread. W transposed in smem (pad 129).
// MODE 0: read desc1|desc2 rows, write HT.  MODE 1: read XT, write HT.
// MODE 2: read XT, write H (row-major).
template <int MODE>
__global__ void gemmT(const float* __restrict__ XT, const float* __restrict__ d1,
                      const float* __restrict__ d2, const float* __restrict__ W,
                      float* __restrict__ OUT) {
    __shared__ float Wt[64 * 129];
    __shared__ __align__(16) float xs[16][128];
    int tid = threadIdx.x;
    int bx = blockIdx.x;
    int cs = (bx & 1) * 64;
    int n0 = (bx >> 1) * 16;
    int c = tid & 63;
    int rh = tid >> 6;

    // W[k][cs..cs+63] transposed into Wt[c][k]
#pragma unroll
    for (int i = 0; i < 16; i++) {
        int f = tid + i * 128;
        int k = f >> 4, cq = f & 15;
        float4 w4 = *reinterpret_cast<const float4*>(W + k * F + cs + cq * 4);
        Wt[(cq * 4 + 0) * 129 + k] = w4.x;
        Wt[(cq * 4 + 1) * 129 + k] = w4.y;
        Wt[(cq * 4 + 2) * 129 + k] = w4.z;
        Wt[(cq * 4 + 3) * 129 + k] = w4.w;
    }
    // 16 rows of input into xs[r][k]
    if (MODE == 0) {
#pragma unroll
        for (int i = 0; i < 4; i++) {
            int f = tid + i * 128;
            int r = f >> 5, cq = f & 31;
            int n = n0 + r;
            float4 x4 = (n < 512) ? reinterpret_cast<const float4*>(d1)[n * 32 + cq]
                                  : reinterpret_cast<const float4*>(d2)[(n - 512) * 32 + cq];
            *reinterpret_cast<float4*>(&xs[r][cq * 4]) = x4;
        }
    } else {
        const float4* XT4 = reinterpret_cast<const float4*>(XT);
#pragma unroll
        for (int i = 0; i < 4; i++) {
            int u = tid + i * 128;          // 0..511
            int k = u >> 2, q = u & 3;      // feature k, node-quad q
            float4 x4 = XT4[k * 256 + (n0 >> 2) + q];
            xs[q * 4 + 0][k] = x4.x;
            xs[q * 4 + 1][k] = x4.y;
            xs[q * 4 + 2][k] = x4.z;
            xs[q * 4 + 3][k] = x4.w;
        }
    }
    __syncthreads();

    float acc[8] = {0, 0, 0, 0, 0, 0, 0, 0};
#pragma unroll 4
    for (int kq = 0; kq < 32; kq++) {
        float w0 = Wt[c * 129 + kq * 4 + 0];
        float w1 = Wt[c * 129 + kq * 4 + 1];
        float w2 = Wt[c * 129 + kq * 4 + 2];
        float w3 = Wt[c * 129 + kq * 4 + 3];
#pragma unroll
        for (int r = 0; r < 8; r++) {
            float4 x = *reinterpret_cast<const float4*>(&xs[rh * 8 + r][kq * 4]);
            acc[r] = fmaf(x.x, w0, fmaf(x.y, w1, fmaf(x.z, w2, fmaf(x.w, w3, acc[r]))));
        }
    }
    if (MODE == 2) {
#pragma unroll
        for (int r = 0; r < 8; r++) OUT[(n0 + rh * 8 + r) * F + cs + c] = acc[r];
    } else {
        // OUT = HT: contiguous 8 nodes for column cs+c
        float* p = OUT + (cs + c) * NN + n0 + rh * 8;
        *reinterpret_cast<float4*>(p) = make_float4(acc[0], acc[1], acc[2], acc[3]);
        *reinterpret_cast<float4*>(p + 4) = make_float4(acc[4], acc[5], acc[6], acc[7]);
    }
}

// ---------------------------------------------------------------------------
__device__ __forceinline__ float2 warp_incl_scan2(float2 v, int lane) {
#pragma unroll
    for (int d = 1; d < 32; d <<= 1) {
        float x = __shfl_up_sync(0xffffffffu, v.x, d);
        float y = __shfl_up_sync(0xffffffffu, v.y, d);
        if (lane >= d) { v.x += x; v.y += y; }
    }
    return v;
}
__device__ __forceinline__ float2 warp_incl_sufscan2(float2 v, int lane) {
#pragma unroll
    for (int d = 1; d < 32; d <<= 1) {
        float x = __shfl_down_sync(0xffffffffu, v.x, d);
        float y = __shfl_down_sync(0xffffffffu, v.y, d);
        if (lane + d < 32) { v.x += x; v.y += y; }
    }
    return v;
}
__device__ __forceinline__ void ce(float& a, float& va, float& b, float& vb, bool up) {
    if ((a > b) == up) {
        float t = a; a = b; b = t;
        float tv = va; va = vb; vb = tv;
    }
}

// ---------------------------------------------------------------------------
// GAT attention (128 heads, C=1), 1 head/block, grid (128, 2), 128 threads.
// All loads/stores coalesced via feature-major HT/XT. Register/shuffle bitonic
// sort of 512 src scores, exact suffix/prefix branch sums, 9-step binary
// search per dst. ELU fused. Output written to XT (feature-major).
template <bool CROSS>
__global__ void attnT(const float* __restrict__ HT, const float* __restrict__ a_src,
                      const float* __restrict__ a_dst, const float* __restrict__ bias,
                      float* __restrict__ XTo) {
    __shared__ float sK[512];
    __shared__ float sV[512];
    __shared__ __align__(16) float4 sSP[513];  // (suf1, suf1v, pre2, pre2v)
    __shared__ float2 wt1[4], wt2[4];

    int t = threadIdx.x;        // 0..127
    int lane = t & 31;
    int w = t >> 5;
    int h = blockIdx.x;
    int dg = blockIdx.y;
    int sg = CROSS ? (1 - dg) : dg;

    float asrc = a_src[h], adst = a_dst[h], bh = bias[h];

    float k[4], v[4], Hd[4];
    {
        float4 v4 = *reinterpret_cast<const float4*>(HT + h * NN + sg * 512 + t * 4);
        float4 h4 = *reinterpret_cast<const float4*>(HT + h * NN + dg * 512 + t * 4);
        v[0] = v4.x; v[1] = v4.y; v[2] = v4.z; v[3] = v4.w;
        Hd[0] = h4.x; Hd[1] = h4.y; Hd[2] = h4.z; Hd[3] = h4.w;
#pragma unroll
        for (int e = 0; e < 4; e++) k[e] = v[e] * asrc;
    }

    // bitonic sort ascending; element i = t*4+e
    for (int K2 = 2; K2 <= 512; K2 <<= 1) {
        for (int J = K2 >> 1; J >= 4; J >>= 1) {
            bool up = (((t * 4) & K2) == 0);
            if (J >= 128) {
                int d = J >> 2;
                bool low = ((t & d) == 0);
                bool want_small = (low == up);
                __syncthreads();
#pragma unroll
                for (int e = 0; e < 4; e++) {
                    sK[t * 4 + e] = k[e];
                    sV[t * 4 + e] = v[e];
                }
                __syncthreads();
#pragma unroll
                for (int e = 0; e < 4; e++) {
                    int p = (t * 4 + e) ^ J;
                    float ko = sK[p];
                    float vo = sV[p];
                    bool take = want_small ? (ko < k[e]) : (ko > k[e]);
                    if (take) { k[e] = ko; v[e] = vo; }
                }
            } else {
                int d = J >> 2;  // lane distance 1..16
                bool low = ((t & d) == 0);
                bool want_small = (low == up);
#pragma unroll
                for (int e = 0; e < 4; e++) {
                    float ko = __shfl_xor_sync(0xffffffffu, k[e], d);
                    float vo = __shfl_xor_sync(0xffffffffu, v[e], d);
                    bool take = want_small ? (ko < k[e]) : (ko > k[e]);
                    if (take) { k[e] = ko; v[e] = vo; }
                }
            }
        }
        if (K2 == 2) {
            ce(k[0], v[0], k[1], v[1], true);
            ce(k[2], v[2], k[3], v[3], false);
        } else {
            bool up = (((t * 4) & K2) == 0);
            ce(k[0], v[0], k[2], v[2], up);
            ce(k[1], v[1], k[3], v[3], up);
            ce(k[0], v[0], k[1], v[1], up);
            ce(k[2], v[2], k[3], v[3], up);
        }
    }

    __syncthreads();
#pragma unroll
    for (int e = 0; e < 4; e++) sK[t * 4 + e] = k[e];
    __syncthreads();
    float M = sK[511];

    // local scans over the thread's 4 sorted elements
    float2 tp1[4], lp2[4], lp1[4];
    float2 c2 = make_float2(0.f, 0.f);
#pragma unroll
    for (int e = 0; e < 4; e++) {
        float q1 = __expf(k[e] - M);
        float q2 = __expf(NSLOPE * (k[e] - M));
        tp1[e] = make_float2(q1, q1 * v[e]);
        c2.x += q2; c2.y += q2 * v[e];
        lp2[e] = c2;
    }
    float2 c1 = make_float2(0.f, 0.f);
#pragma unroll
    for (int e = 3; e >= 0; e--) {
        c1.x += tp1[e].x; c1.y += tp1[e].y;
        lp1[e] = c1;
    }

    float2 tincl = warp_incl_scan2(lp2[3], lane);
    float2 texcl;
    texcl.x = __shfl_up_sync(0xffffffffu, tincl.x, 1);
    texcl.y = __shfl_up_sync(0xffffffffu, tincl.y, 1);
    if (lane == 0) texcl = make_float2(0.f, 0.f);
    if (lane == 31) wt2[w] = tincl;

    float2 sincl = warp_incl_sufscan2(lp1[0], lane);
    float2 sexcl;
    sexcl.x = __shfl_down_sync(0xffffffffu, sincl.x, 1);
    sexcl.y = __shfl_down_sync(0xffffffffu, sincl.y, 1);
    if (lane == 31) sexcl = make_float2(0.f, 0.f);
    if (lane == 0) wt1[w] = sincl;
    __syncthreads();

    float2 base2 = texcl, base1 = sexcl;
#pragma unroll
    for (int ww = 0; ww < 4; ww++) {
        if (ww < w) { base2.x += wt2[ww].x; base2.y += wt2[ww].y; }
        if (ww > w) { base1.x += wt1[ww].x; base1.y += wt1[ww].y; }
    }
#pragma unroll
    for (int e = 0; e < 4; e++) {
        int j = t * 4 + e;
        float2 pre = base2;
        if (e > 0) { pre.x += lp2[e - 1].x; pre.y += lp2[e - 1].y; }
        sSP[j] = make_float4(base1.x + lp1[e].x, base1.y + lp1[e].y, pre.x, pre.y);
    }
    if (t == 127) sSP[512] = make_float4(0.f, 0.f, base2.x + lp2[3].x, base2.y + lp2[3].y);
    __syncthreads();

    // per-dst: binary search rank of threshold -ad, combine branch sums
    float adv[4], th[4];
    int pos[4];
#pragma unroll
    for (int e = 0; e < 4; e++) {
        adv[e] = Hd[e] * adst;
        th[e] = -adv[e];
        pos[e] = 0;
    }
#pragma unroll
    for (int half = 256; half >= 1; half >>= 1) {
#pragma unroll
        for (int e = 0; e < 4; e++)
            if (sK[pos[e] + half - 1] <= th[e]) pos[e] += half;
    }
#pragma unroll
    for (int e = 0; e < 4; e++)
        if (sK[pos[e]] <= th[e]) pos[e]++;

    float oval[4];
#pragma unroll
    for (int e = 0; e < 4; e++) {
        float4 S = sSP[pos[e]];
        float ad = adv[e];
        float T = M + ad;
        float tmax = T, ts = 0.f;
        if (CROSS) {
            ts = Hd[e] * asrc + ad;
            tmax = fmaxf(tmax, ts);
        }
        float C = lrelu(tmax);
        float f1 = __expf(T - C);
        float f2 = __expf(NSLOPE * T - C);
        float num = f1 * S.y + f2 * S.w;
        float den = f1 * S.x + f2 * S.z;
        if (CROSS) {
            float ws = __expf(lrelu(ts) - C);
            num = fmaf(ws, Hd[e], num);
            den += ws;
        }
        float o = num / (den + 1e-16f) + bh;
        oval[e] = o > 0.f ? o : expm1f(o);  // ELU
    }
    *reinterpret_cast<float4*>(XTo + h * NN + dg * 512 + t * 4) =
        make_float4(oval[0], oval[1], oval[2], oval[3]);
}

// ---------------------------------------------------------------------------
__global__ void dots_kernel(const float* __restrict__ H, const float* __restrict__ a_s,
                            const float* __restrict__ a_d, float* __restrict__ asf,
                            float* __restrict__ adf) {
    int n = blockIdx.x, t = threadIdx.x;
    float h = H[n * F + t];
    float s1 = h * a_s[t];
    float s2 = h * a_d[t];
#pragma unroll
    for (int o = 16; o; o >>= 1) {
        s1 += __shfl_xor_sync(0xffffffffu, s1, o);
        s2 += __shfl_xor_sync(0xffffffffu, s2, o);
    }
    __shared__ float r1[4], r2[4];
    if ((t & 31) == 0) { r1[t >> 5] = s1; r2[t >> 5] = s2; }
    __syncthreads();
    if (t == 0) {
        asf[n] = r1[0] + r1[1] + r1[2] + r1[3];
        adf[n] = r2[0] + r2[1] + r2[2] + r2[3];
    }
}

// final cross-attention: 8 dsts/block, 256 threads (128 cols x 2 s-halves)
__global__ void final_attn(const float* __restrict__ H, const float* __restrict__ asf,
                           const float* __restrict__ adf, const float* __restrict__ bias,
                           float* __restrict__ out) {
    int d0 = blockIdx.x * 8;
    int dg = d0 >> 9;
    int sg = 1 - dg;
    int tid = threadIdx.x;
    int col = tid & 127, sh = tid >> 7;
    int w = tid >> 5, lane = tid & 31;

    __shared__ float sAsf[512];
    __shared__ float4 swq[512][2];
    __shared__ float sAdf[8], sM[8], sSelf[8], sDen[8];
    __shared__ float pr[8][128];
    __shared__ float dred[8][256];
    __shared__ float red[8];

    float mloc = -1e30f;
    for (int s = tid; s < 512; s += 256) {
        float v = asf[sg * 512 + s];
        sAsf[s] = v;
        mloc = fmaxf(mloc, v);
    }
#pragma unroll
    for (int o = 16; o; o >>= 1) mloc = fmaxf(mloc, __shfl_xor_sync(0xffffffffu, mloc, o));
    if (lane == 0) red[w] = mloc;
    __syncthreads();
    float maxasf = red[0];
#pragma unroll
    for (int ww = 1; ww < 8; ww++) maxasf = fmaxf(maxasf, red[ww]);

    if (tid < 8) {
        int dn = d0 + tid;
        float ad = adf[dn];
        float ts = asf[dn] + ad;
        float tmax = fmaxf(maxasf + ad, ts);
        float mm = lrelu(tmax);
        sAdf[tid] = ad;
        sM[tid] = mm;
        sSelf[tid] = __expf(lrelu(ts) - mm);
    }
    __syncthreads();

    float dl[8] = {0, 0, 0, 0, 0, 0, 0, 0};
    for (int s = tid; s < 512; s += 256) {
        float a = sAsf[s];
        float wv[8];
#pragma unroll
        for (int d = 0; d < 8; d++) {
            wv[d] = __expf(lrelu(a + sAdf[d]) - sM[d]);
            dl[d] += wv[d];
        }
        swq[s][0] = make_float4(wv[0], wv[1], wv[2], wv[3]);
        swq[s][1] = make_float4(wv[4], wv[5], wv[6], wv[7]);
    }
#pragma unroll
    for (int d = 0; d < 8; d++) dred[d][tid] = dl[d];
    __syncthreads();
    {
        float x = dred[w][lane] + dred[w][lane + 32] + dred[w][lane + 64] + dred[w][lane + 96] +
                  dred[w][lane + 128] + dred[w][lane + 160] + dred[w][lane + 192] + dred[w][lane + 224];
#pragma unroll
        for (int o = 16; o; o >>= 1) x += __shfl_xor_sync(0xffffffffu, x, o);
        if (lane == 0) sDen[w] = x;
    }
    __syncthreads();

    float acc[8] = {0, 0, 0, 0, 0, 0, 0, 0};
    const float* Hs = H + (sg * 512 + sh * 256) * F + col;
#pragma unroll 2
    for (int s = 0; s < 256; s++) {
        float hv = Hs[s * F];
        int ss = sh * 256 + s;
        float4 w0 = swq[ss][0];
        float4 w1 = swq[ss][1];
        acc[0] = fmaf(w0.x, hv, acc[0]);
        acc[1] = fmaf(w0.y, hv, acc[1]);
        acc[2] = fmaf(w0.z, hv, acc[2]);
        acc[3] = fmaf(w0.w, hv, acc[3]);
        acc[4] = fmaf(w1.x, hv, acc[4]);
        acc[5] = fmaf(w1.y, hv, acc[5]);
        acc[6] = fmaf(w1.z, hv, acc[6]);
        acc[7] = fmaf(w1.w, hv, acc[7]);
    }
    if (sh) {
#pragma unroll
        for (int d = 0; d < 8; d++) pr[d][col] = acc[d];
    }
    __syncthreads();
    if (!sh) {
        float bc = bias[col];
#pragma unroll
        for (int d = 0; d < 8; d++) {
            int dn = d0 + d;
            float Hdv = H[dn * F + col];
            float num = acc[d] + pr[d][col] + sSelf[d] * Hdv;
            out[dn * F + col] = num / (sDen[d] + sSelf[d] + 1e-16f) + bc;
        }
    }
}

// ---------------------------------------------------------------------------
extern "C" void kernel_launch(void* const* d_in, const int* in_sizes, int n_in,
                              void* d_out, int out_size) {
    const float* desc1 = (const float*)d_in[0];
    const float* desc2 = (const float*)d_in[1];
    const float* W1 = (const float*)d_in[2];
    const float* as1 = (const float*)d_in[3];
    const float* ad1 = (const float*)d_in[4];
    const float* b1 = (const float*)d_in[5];
    const float* W2 = (const float*)d_in[6];
    const float* as2 = (const float*)d_in[7];
    const float* ad2 = (const float*)d_in[8];
    const float* b2 = (const float*)d_in[9];
    float* out = (float*)d_out;

    float *XT, *HT, *H, *asf, *adf;
    cudaGetSymbolAddress((void**)&XT, g_XT);
    cudaGetSymbolAddress((void**)&HT, g_HT);
    cudaGetSymbolAddress((void**)&H, g_H);
    cudaGetSymbolAddress((void**)&asf, g_asf);
    cudaGetSymbolAddress((void**)&adf, g_adf);

    dim3 ag(128, 2);
    // conv1: inside (concat fused into gemm)
    gemmT<0><<<128, 128>>>(nullptr, desc1, desc2, W1, HT);
    attnT<false><<<ag, 128>>>(HT, as1, ad1, b1, XT);
    // conv2: cross
    gemmT<1><<<128, 128>>>(XT, nullptr, nullptr, W1, HT);
    attnT<true><<<ag, 128>>>(HT, as1, ad1, b1, XT);
    // conv3: inside
    gemmT<1><<<128, 128>>>(XT, nullptr, nullptr, W1, HT);
    attnT<false><<<ag, 128>>>(HT, as1, ad1, b1, XT);
    // conv4: cross
    gemmT<1><<<128, 128>>>(XT, nullptr, nullptr, W1, HT);
    attnT<true><<<ag, 128>>>(HT, as1, ad1, b1, XT);
    // final conv: cross, heads=1, out_ch=128, no ELU (row-major H)
    gemmT<2><<<128, 128>>>(XT, nullptr, nullptr, W2, H);
    dots_kernel<<<1024, 128>>>(H, as2, ad2, asf, adf);
    final_attn<<<128, 256>>>(H, asf, adf, b2, out);
}

// round 6
// speedup vs baseline: 1.2587x; 1.1574x over previous
#include <cuda_runtime.h>
#include <math.h>

#define NSLOPE 0.2f
#define NN 1024
#define F 128

__device__ float g_XT[NN * F];   // feature-major activations [f][n]
__device__ float g_HT[NN * F];   // feature-major conv features [f][n]
__device__ float g_H[NN * F];    // row-major (final conv only)
__device__ float g_asf[NN];
__device__ float g_adf[NN];

__device__ __forceinline__ float lrelu(float x) { return x > 0.f ? x : NSLOPE * x; }

// ---------------------------------------------------------------------------
// GEMM. grid 256: (row-block 0..127) x (col-half 0..1); block 128 threads.
// 8 rows x 64 cols per block, 4 rows/thread. W transposed in smem (pad 129).
// MODE 0: read desc1|desc2 rows, write HT.  MODE 1: read XT, write HT.
// MODE 2: read XT, write H (row-major).
template <int MODE>
__global__ void gemmT(const float* __restrict__ XT, const float* __restrict__ d1,
                      const float* __restrict__ d2, const float* __restrict__ W,
                      float* __restrict__ OUT) {
    __shared__ float Wt[64 * 129];
    __shared__ __align__(16) float xs[8][128];
    int tid = threadIdx.x;
    int bx = blockIdx.x;
    int cs = (bx & 1) * 64;
    int n0 = (bx >> 1) * 8;
    int c = tid & 63;
    int rh = tid >> 6;

    // W[k][cs..cs+63] transposed into Wt[c][k]
#pragma unroll
    for (int i = 0; i < 16; i++) {
        int f = tid + i * 128;
        int k = f >> 4, cq = f & 15;
        float4 w4 = *reinterpret_cast<const float4*>(W + k * F + cs + cq * 4);
        Wt[(cq * 4 + 0) * 129 + k] = w4.x;
        Wt[(cq * 4 + 1) * 129 + k] = w4.y;
        Wt[(cq * 4 + 2) * 129 + k] = w4.z;
        Wt[(cq * 4 + 3) * 129 + k] = w4.w;
    }
    // 8 rows of input into xs[r][k]
    if (MODE == 0) {
#pragma unroll
        for (int i = 0; i < 2; i++) {
            int f = tid + i * 128;
            int r = f >> 5, cq = f & 31;
            int n = n0 + r;
            float4 x4 = (n < 512) ? reinterpret_cast<const float4*>(d1)[n * 32 + cq]
                                  : reinterpret_cast<const float4*>(d2)[(n - 512) * 32 + cq];
            *reinterpret_cast<float4*>(&xs[r][cq * 4]) = x4;
        }
    } else {
        const float4* XT4 = reinterpret_cast<const float4*>(XT);
#pragma unroll
        for (int i = 0; i < 2; i++) {
            int u = tid + i * 128;          // 0..255
            int k = u >> 1, q = u & 1;      // feature k, node-quad q
            float4 x4 = XT4[k * 256 + (n0 >> 2) + q];
            xs[q * 4 + 0][k] = x4.x;
            xs[q * 4 + 1][k] = x4.y;
            xs[q * 4 + 2][k] = x4.z;
            xs[q * 4 + 3][k] = x4.w;
        }
    }
    __syncthreads();

    float acc[4] = {0, 0, 0, 0};
#pragma unroll 4
    for (int kq = 0; kq < 32; kq++) {
        float w0 = Wt[c * 129 + kq * 4 + 0];
        float w1 = Wt[c * 129 + kq * 4 + 1];
        float w2 = Wt[c * 129 + kq * 4 + 2];
        float w3 = Wt[c * 129 + kq * 4 + 3];
#pragma unroll
        for (int r = 0; r < 4; r++) {
            float4 x = *reinterpret_cast<const float4*>(&xs[rh * 4 + r][kq * 4]);
            acc[r] = fmaf(x.x, w0, fmaf(x.y, w1, fmaf(x.z, w2, fmaf(x.w, w3, acc[r]))));
        }
    }
    if (MODE == 2) {
#pragma unroll
        for (int r = 0; r < 4; r++) OUT[(n0 + rh * 4 + r) * F + cs + c] = acc[r];
    } else {
        float* p = OUT + (cs + c) * NN + n0 + rh * 4;
        *reinterpret_cast<float4*>(p) = make_float4(acc[0], acc[1], acc[2], acc[3]);
    }
}

// ---------------------------------------------------------------------------
__device__ __forceinline__ float2 warp_incl_scan2(float2 v, int lane) {
#pragma unroll
    for (int d = 1; d < 32; d <<= 1) {
        float x = __shfl_up_sync(0xffffffffu, v.x, d);
        float y = __shfl_up_sync(0xffffffffu, v.y, d);
        if (lane >= d) { v.x += x; v.y += y; }
    }
    return v;
}
__device__ __forceinline__ float2 warp_incl_sufscan2(float2 v, int lane) {
#pragma unroll
    for (int d = 1; d < 32; d <<= 1) {
        float x = __shfl_down_sync(0xffffffffu, v.x, d);
        float y = __shfl_down_sync(0xffffffffu, v.y, d);
        if (lane + d < 32) { v.x += x; v.y += y; }
    }
    return v;
}
__device__ __forceinline__ void ce(float& a, float& va, float& b, float& vb, bool up) {
    if ((a > b) == up) {
        float t = a; a = b; b = t;
        float tv = va; va = vb; vb = tv;
    }
}

// ---------------------------------------------------------------------------
// GAT attention (128 heads, C=1), 1 head/block, grid (128, 2), 256 threads,
// 2 elements/thread (2048 warps chip-wide for latency hiding).
// Register/shuffle bitonic sort of 512 src scores, exact suffix/prefix branch
// sums, 9-step binary search per dst. ELU fused. Feature-major I/O.
template <bool CROSS>
__global__ void attnT(const float* __restrict__ HT, const float* __restrict__ a_src,
                      const float* __restrict__ a_dst, const float* __restrict__ bias,
                      float* __restrict__ XTo) {
    __shared__ float sK[512];
    __shared__ float sV[512];
    __shared__ __align__(16) float4 sSP[513];  // (suf1, suf1v, pre2, pre2v)
    __shared__ float2 wt1[8], wt2[8];

    int t = threadIdx.x;        // 0..255
    int lane = t & 31;
    int w = t >> 5;             // warp 0..7
    int h = blockIdx.x;
    int dg = blockIdx.y;
    int sg = CROSS ? (1 - dg) : dg;

    float asrc = a_src[h], adst = a_dst[h], bh = bias[h];

    float k[2], v[2], Hd[2];
    {
        float2 v2 = *reinterpret_cast<const float2*>(HT + h * NN + sg * 512 + t * 2);
        float2 h2 = *reinterpret_cast<const float2*>(HT + h * NN + dg * 512 + t * 2);
        v[0] = v2.x; v[1] = v2.y;
        Hd[0] = h2.x; Hd[1] = h2.y;
        k[0] = v[0] * asrc;
        k[1] = v[1] * asrc;
    }

    // bitonic sort ascending; element i = t*2+e
    for (int K2 = 2; K2 <= 512; K2 <<= 1) {
        for (int J = K2 >> 1; J >= 2; J >>= 1) {
            bool up = (((t * 2) & K2) == 0);
            if (J >= 64) {
                // smem exchange (thread distance >= 32)
                __syncthreads();
                sK[t * 2] = k[0]; sK[t * 2 + 1] = k[1];
                sV[t * 2] = v[0]; sV[t * 2 + 1] = v[1];
                __syncthreads();
                int d = J >> 1;
                bool low = ((t & d) == 0);
                bool want_small = (low == up);
#pragma unroll
                for (int e = 0; e < 2; e++) {
                    int p = (t * 2 + e) ^ J;
                    float ko = sK[p], vo = sV[p];
                    bool take = want_small ? (ko < k[e]) : (ko > k[e]);
                    if (take) { k[e] = ko; v[e] = vo; }
                }
            } else {
                int d = J >> 1;  // lane distance 1..16
                bool low = ((t & d) == 0);
                bool want_small = (low == up);
#pragma unroll
                for (int e = 0; e < 2; e++) {
                    float ko = __shfl_xor_sync(0xffffffffu, k[e], d);
                    float vo = __shfl_xor_sync(0xffffffffu, v[e], d);
                    bool take = want_small ? (ko < k[e]) : (ko > k[e]);
                    if (take) { k[e] = ko; v[e] = vo; }
                }
            }
        }
        // J == 1: intra-thread pair
        {
            bool up = (((t * 2) & K2) == 0);
            ce(k[0], v[0], k[1], v[1], up);
        }
    }

    __syncthreads();
    sK[t * 2] = k[0]; sK[t * 2 + 1] = k[1];
    __syncthreads();
    float M = sK[511];

    // local scans over the thread's 2 sorted elements
    float2 tp1[2], lp2[2], lp1[2];
    float2 c2 = make_float2(0.f, 0.f);
#pragma unroll
    for (int e = 0; e < 2; e++) {
        float q1 = __expf(k[e] - M);
        float q2 = __expf(NSLOPE * (k[e] - M));
        tp1[e] = make_float2(q1, q1 * v[e]);
        c2.x += q2; c2.y += q2 * v[e];
        lp2[e] = c2;
    }
    float2 c1 = make_float2(0.f, 0.f);
#pragma unroll
    for (int e = 1; e >= 0; e--) {
        c1.x += tp1[e].x; c1.y += tp1[e].y;
        lp1[e] = c1;
    }

    float2 tincl = warp_incl_scan2(lp2[1], lane);
    float2 texcl;
    texcl.x = __shfl_up_sync(0xffffffffu, tincl.x, 1);
    texcl.y = __shfl_up_sync(0xffffffffu, tincl.y, 1);
    if (lane == 0) texcl = make_float2(0.f, 0.f);
    if (lane == 31) wt2[w] = tincl;

    float2 sincl = warp_incl_sufscan2(lp1[0], lane);
    float2 sexcl;
    sexcl.x = __shfl_down_sync(0xffffffffu, sincl.x, 1);
    sexcl.y = __shfl_down_sync(0xffffffffu, sincl.y, 1);
    if (lane == 31) sexcl = make_float2(0.f, 0.f);
    if (lane == 0) wt1[w] = sincl;
    __syncthreads();

    float2 base2 = texcl, base1 = sexcl;
#pragma unroll
    for (int ww = 0; ww < 8; ww++) {
        if (ww < w) { base2.x += wt2[ww].x; base2.y += wt2[ww].y; }
        if (ww > w) { base1.x += wt1[ww].x; base1.y += wt1[ww].y; }
    }
#pragma unroll
    for (int e = 0; e < 2; e++) {
        int j = t * 2 + e;
        float2 pre = base2;
        if (e > 0) { pre.x += lp2[0].x; pre.y += lp2[0].y; }
        sSP[j] = make_float4(base1.x + lp1[e].x, base1.y + lp1[e].y, pre.x, pre.y);
    }
    if (t == 255) sSP[512] = make_float4(0.f, 0.f, base2.x + lp2[1].x, base2.y + lp2[1].y);
    __syncthreads();

    // per-dst: binary search rank of threshold -ad, combine branch sums
    float adv[2], th[2];
    int pos[2];
#pragma unroll
    for (int e = 0; e < 2; e++) {
        adv[e] = Hd[e] * adst;
        th[e] = -adv[e];
        pos[e] = 0;
    }
#pragma unroll
    for (int half = 256; half >= 1; half >>= 1) {
#pragma unroll
        for (int e = 0; e < 2; e++)
            if (sK[pos[e] + half - 1] <= th[e]) pos[e] += half;
    }
#pragma unroll
    for (int e = 0; e < 2; e++)
        if (sK[pos[e]] <= th[e]) pos[e]++;

    float oval[2];
#pragma unroll
    for (int e = 0; e < 2; e++) {
        float4 S = sSP[pos[e]];
        float ad = adv[e];
        float T = M + ad;
        float tmax = T, ts = 0.f;
        if (CROSS) {
            ts = Hd[e] * asrc + ad;
            tmax = fmaxf(tmax, ts);
        }
        float C = lrelu(tmax);
        float f1 = __expf(T - C);
        float f2 = __expf(NSLOPE * T - C);
        float num = f1 * S.y + f2 * S.w;
        float den = f1 * S.x + f2 * S.z;
        if (CROSS) {
            float ws = __expf(lrelu(ts) - C);
            num = fmaf(ws, Hd[e], num);
            den += ws;
        }
        float o = num / (den + 1e-16f) + bh;
        oval[e] = o > 0.f ? o : expm1f(o);  // ELU
    }
    *reinterpret_cast<float2*>(XTo + h * NN + dg * 512 + t * 2) =
        make_float2(oval[0], oval[1]);
}

// ---------------------------------------------------------------------------
__global__ void dots_kernel(const float* __restrict__ H, const float* __restrict__ a_s,
                            const float* __restrict__ a_d, float* __restrict__ asf,
                            float* __restrict__ adf) {
    int n = blockIdx.x, t = threadIdx.x;
    float h = H[n * F + t];
    float s1 = h * a_s[t];
    float s2 = h * a_d[t];
#pragma unroll
    for (int o = 16; o; o >>= 1) {
        s1 += __shfl_xor_sync(0xffffffffu, s1, o);
        s2 += __shfl_xor_sync(0xffffffffu, s2, o);
    }
    __shared__ float r1[4], r2[4];
    if ((t & 31) == 0) { r1[t >> 5] = s1; r2[t >> 5] = s2; }
    __syncthreads();
    if (t == 0) {
        asf[n] = r1[0] + r1[1] + r1[2] + r1[3];
        adf[n] = r2[0] + r2[1] + r2[2] + r2[3];
    }
}

// final cross-attention: 8 dsts/block, 256 threads (128 cols x 2 s-halves)
__global__ void final_attn(const float* __restrict__ H, const float* __restrict__ asf,
                           const float* __restrict__ adf, const float* __restrict__ bias,
                           float* __restrict__ out) {
    int d0 = blockIdx.x * 8;
    int dg = d0 >> 9;
    int sg = 1 - dg;
    int tid = threadIdx.x;
    int col = tid & 127, sh = tid >> 7;
    int w = tid >> 5, lane = tid & 31;

    __shared__ float sAsf[512];
    __shared__ float4 swq[512][2];
    __shared__ float sAdf[8], sM[8], sSelf[8], sDen[8];
    __shared__ float pr[8][128];
    __shared__ float dred[8][256];
    __shared__ float red[8];

    float mloc = -1e30f;
    for (int s = tid; s < 512; s += 256) {
        float v = asf[sg * 512 + s];
        sAsf[s] = v;
        mloc = fmaxf(mloc, v);
    }
#pragma unroll
    for (int o = 16; o; o >>= 1) mloc = fmaxf(mloc, __shfl_xor_sync(0xffffffffu, mloc, o));
    if (lane == 0) red[w] = mloc;
    __syncthreads();
    float maxasf = red[0];
#pragma unroll
    for (int ww = 1; ww < 8; ww++) maxasf = fmaxf(maxasf, red[ww]);

    if (tid < 8) {
        int dn = d0 + tid;
        float ad = adf[dn];
        float ts = asf[dn] + ad;
        float tmax = fmaxf(maxasf + ad, ts);
        float mm = lrelu(tmax);
        sAdf[tid] = ad;
        sM[tid] = mm;
        sSelf[tid] = __expf(lrelu(ts) - mm);
    }
    __syncthreads();

    float dl[8] = {0, 0, 0, 0, 0, 0, 0, 0};
    for (int s = tid; s < 512; s += 256) {
        float a = sAsf[s];
        float wv[8];
#pragma unroll
        for (int d = 0; d < 8; d++) {
            wv[d] = __expf(lrelu(a + sAdf[d]) - sM[d]);
            dl[d] += wv[d];
        }
        swq[s][0] = make_float4(wv[0], wv[1], wv[2], wv[3]);
        swq[s][1] = make_float4(wv[4], wv[5], wv[6], wv[7]);
    }
#pragma unroll
    for (int d = 0; d < 8; d++) dred[d][tid] = dl[d];
    __syncthreads();
    {
        float x = dred[w][lane] + dred[w][lane + 32] + dred[w][lane + 64] + dred[w][lane + 96] +
                  dred[w][lane + 128] + dred[w][lane + 160] + dred[w][lane + 192] + dred[w][lane + 224];
#pragma unroll
        for (int o = 16; o; o >>= 1) x += __shfl_xor_sync(0xffffffffu, x, o);
        if (lane == 0) sDen[w] = x;
    }
    __syncthreads();

    float acc[8] = {0, 0, 0, 0, 0, 0, 0, 0};
    const float* Hs = H + (sg * 512 + sh * 256) * F + col;
#pragma unroll 2
    for (int s = 0; s < 256; s++) {
        float hv = Hs[s * F];
        int ss = sh * 256 + s;
        float4 w0 = swq[ss][0];
        float4 w1 = swq[ss][1];
        acc[0] = fmaf(w0.x, hv, acc[0]);
        acc[1] = fmaf(w0.y, hv, acc[1]);
        acc[2] = fmaf(w0.z, hv, acc[2]);
        acc[3] = fmaf(w0.w, hv, acc[3]);
        acc[4] = fmaf(w1.x, hv, acc[4]);
        acc[5] = fmaf(w1.y, hv, acc[5]);
        acc[6] = fmaf(w1.z, hv, acc[6]);
        acc[7] = fmaf(w1.w, hv, acc[7]);
    }
    if (sh) {
#pragma unroll
        for (int d = 0; d < 8; d++) pr[d][col] = acc[d];
    }
    __syncthreads();
    if (!sh) {
        float bc = bias[col];
#pragma unroll
        for (int d = 0; d < 8; d++) {
            int dn = d0 + d;
            float Hdv = H[dn * F + col];
            float num = acc[d] + pr[d][col] + sSelf[d] * Hdv;
            out[dn * F + col] = num / (sDen[d] + sSelf[d] + 1e-16f) + bc;
        }
    }
}

// ---------------------------------------------------------------------------
extern "C" void kernel_launch(void* const* d_in, const int* in_sizes, int n_in,
                              void* d_out, int out_size) {
    const float* desc1 = (const float*)d_in[0];
    const float* desc2 = (const float*)d_in[1];
    const float* W1 = (const float*)d_in[2];
    const float* as1 = (const float*)d_in[3];
    const float* ad1 = (const float*)d_in[4];
    const float* b1 = (const float*)d_in[5];
    const float* W2 = (const float*)d_in[6];
    const float* as2 = (const float*)d_in[7];
    const float* ad2 = (const float*)d_in[8];
    const float* b2 = (const float*)d_in[9];
    float* out = (float*)d_out;

    float *XT, *HT, *H, *asf, *adf;
    cudaGetSymbolAddress((void**)&XT, g_XT);
    cudaGetSymbolAddress((void**)&HT, g_HT);
    cudaGetSymbolAddress((void**)&H, g_H);
    cudaGetSymbolAddress((void**)&asf, g_asf);
    cudaGetSymbolAddress((void**)&adf, g_adf);

    dim3 ag(128, 2);
    // conv1: inside (concat fused into gemm)
    gemmT<0><<<256, 128>>>(nullptr, desc1, desc2, W1, HT);
    attnT<false><<<ag, 256>>>(HT, as1, ad1, b1, XT);
    // conv2: cross
    gemmT<1><<<256, 128>>>(XT, nullptr, nullptr, W1, HT);
    attnT<true><<<ag, 256>>>(HT, as1, ad1, b1, XT);
    // conv3: inside
    gemmT<1><<<256, 128>>>(XT, nullptr, nullptr, W1, HT);
    attnT<false><<<ag, 256>>>(HT, as1, ad1, b1, XT);
    // conv4: cross
    gemmT<1><<<256, 128>>>(XT, nullptr, nullptr, W1, HT);
    attnT<true><<<ag, 256>>>(HT, as1, ad1, b1, XT);
    // final conv: cross, heads=1, out_ch=128, no ELU (row-major H)
    gemmT<2><<<256, 128>>>(XT, nullptr, nullptr, W2, H);
    dots_kernel<<<1024, 128>>>(H, as2, ad2, asf, adf);
    final_attn<<<128, 256>>>(H, asf, adf, b2, out);
}